// round 7
// baseline (speedup 1.0000x reference)
#include <cuda_runtime.h>
#include <cuda_fp16.h>
#include <math.h>

#define NN 100000
#define NE 1600000
#define NC 40
#define CJ 10              // 40 floats = 10 float4 chunks (fp32 buffers)
#define HJ 5               // 40 halves = 5 uint4 chunks (fp16 buffers)
#define NT 50000
#define NC4 (NN*CJ)
#define NH4 (NN*HJ)
#define SCAN_T 1024
#define SCAN_B ((NN + SCAN_T - 1)/SCAN_T)
#define NBIN 256

#define ALPHA_C 0.979f
#define ALPHA_S 0.756f

// ---- scratch (static device globals: allocation-free) ----
static __device__ int    g_deg[NN];       // original-space degree
static __device__ int    g_perm[NN];      // sorted pos -> original id
static __device__ int    g_inv[NN];       // original id -> sorted pos
static __device__ int    g_sdeg[NN];      // sorted-space degree
static __device__ float  g_snorm[NN];     // sorted-space norm
static __device__ int    g_srowptr[NN+1];
static __device__ int    g_scursor[NN];
static __device__ int    g_scolidx[NE];   // sorted ids
static __device__ float  g_scalebuf[NN];
static __device__ uint4  g_h0[NH4];       // fp16 feature buffer (ping), sorted space
static __device__ uint4  g_h1[NH4];       // fp16 feature buffer (pong), sorted space
static __device__ uint4  g_baseh[NH4];    // fp16 (1-alpha)*y0 anchor, sorted space
static __device__ float4 g_y[NC4];        // smoothed_error (fp32), sorted space
static __device__ int    g_bins[NBIN];
static __device__ int    g_bincur[NBIN];
static __device__ int    g_bsum[SCAN_B];
static __device__ double g_sigma;

__global__ void k_init() {
    int v = blockIdx.x*blockDim.x + threadIdx.x;
    if (v < NN) g_deg[v] = 0;
    if (v < NBIN) g_bins[v] = 0;
    if (v == 0) g_sigma = 0.0;
}

__global__ void k_count(const int* __restrict__ dst) {
    int e = blockIdx.x*blockDim.x + threadIdx.x;
    if (e < NE) atomicAdd(&g_deg[dst[e]], 1);
}

__global__ void k_hist() {
    int v = blockIdx.x*blockDim.x + threadIdx.x;
    if (v < NN) {
        int b = g_deg[v]; if (b > NBIN-1) b = NBIN-1;
        atomicAdd(&g_bins[b], 1);
    }
}

// exclusive scan of g_bins[256], one block of 256; also seeds g_bincur
__global__ void k_binscan() {
    __shared__ int wsum[8];
    int t = threadIdx.x;
    int lane = t & 31, w = t >> 5;
    int val = g_bins[t];
    int inc = val;
    #pragma unroll
    for (int o = 1; o < 32; o <<= 1) {
        int x = __shfl_up_sync(0xffffffffu, inc, o);
        if (lane >= o) inc += x;
    }
    if (lane == 31) wsum[w] = inc;
    __syncthreads();
    if (t == 0) {
        int r = 0;
        #pragma unroll
        for (int i = 0; i < 8; i++) { int x = wsum[i]; wsum[i] = r; r += x; }
    }
    __syncthreads();
    int ex = inc - val + wsum[w];
    g_bincur[t] = ex;
}

// scatter nodes into degree-sorted order; build perm/inv/sdeg/snorm
__global__ void k_perm() {
    int v = blockIdx.x*blockDim.x + threadIdx.x;
    if (v >= NN) return;
    int d = g_deg[v];
    int b = d > NBIN-1 ? NBIN-1 : d;
    int p = atomicAdd(&g_bincur[b], 1);
    g_perm[p] = v;
    g_inv[v] = p;
    g_sdeg[p] = d;
    g_snorm[p] = 1.0f / sqrtf((float)(d > 0 ? d : 1));
}

__global__ void k_scan1() {
    __shared__ int sh[32];
    int v = blockIdx.x*SCAN_T + threadIdx.x;
    int d = (v < NN) ? g_sdeg[v] : 0;
    int s = d;
    #pragma unroll
    for (int o = 16; o; o >>= 1) s += __shfl_down_sync(0xffffffffu, s, o);
    if ((threadIdx.x & 31) == 0) sh[threadIdx.x >> 5] = s;
    __syncthreads();
    if (threadIdx.x < 32) {
        int t = sh[threadIdx.x];
        #pragma unroll
        for (int o = 16; o; o >>= 1) t += __shfl_down_sync(0xffffffffu, t, o);
        if (threadIdx.x == 0) g_bsum[blockIdx.x] = t;
    }
}

// parallel exclusive scan of g_bsum[SCAN_B] (SCAN_B=98 <= 128), one block of 128
__global__ void k_scan2() {
    __shared__ int wsum[4];
    int t = threadIdx.x;
    int lane = t & 31, w = t >> 5;
    int val = (t < SCAN_B) ? g_bsum[t] : 0;
    int inc = val;
    #pragma unroll
    for (int o = 1; o < 32; o <<= 1) {
        int x = __shfl_up_sync(0xffffffffu, inc, o);
        if (lane >= o) inc += x;
    }
    if (lane == 31) wsum[w] = inc;
    __syncthreads();
    if (t == 0) {
        int r = 0;
        #pragma unroll
        for (int i = 0; i < 4; i++) { int x = wsum[i]; wsum[i] = r; r += x; }
    }
    __syncthreads();
    if (t < SCAN_B) g_bsum[t] = inc - val + wsum[w];   // exclusive
}

__global__ void k_scan3() {
    __shared__ int wsum[32];
    int v = blockIdx.x*SCAN_T + threadIdx.x;
    int d = (v < NN) ? g_sdeg[v] : 0;
    int lane = threadIdx.x & 31, w = threadIdx.x >> 5;
    int inc = d;
    #pragma unroll
    for (int o = 1; o < 32; o <<= 1) {
        int t = __shfl_up_sync(0xffffffffu, inc, o);
        if (lane >= o) inc += t;
    }
    if (lane == 31) wsum[w] = inc;
    __syncthreads();
    if (w == 0) {
        int t = wsum[lane];
        int ti = t;
        #pragma unroll
        for (int o = 1; o < 32; o <<= 1) {
            int x = __shfl_up_sync(0xffffffffu, ti, o);
            if (lane >= o) ti += x;
        }
        wsum[lane] = ti - t;   // exclusive
    }
    __syncthreads();
    int ex = inc - d + wsum[w] + g_bsum[blockIdx.x];
    if (v < NN) {
        g_srowptr[v] = ex;
        g_scursor[v] = ex;
        if (v == NN-1) g_srowptr[NN] = ex + d;
    }
}

// fill sorted CSR: edges land in row inv[dst], storing sorted src ids
__global__ void k_fill(const int* __restrict__ src, const int* __restrict__ dst) {
    int e = blockIdx.x*blockDim.x + threadIdx.x;
    if (e < NE) {
        int p = g_inv[dst[e]];
        int pos = atomicAdd(&g_scursor[p], 1);
        g_scolidx[pos] = g_inv[src[e]];
    }
}

__global__ void k_zero2() {
    int g = blockIdx.x*blockDim.x + threadIdx.x;
    if (g < NH4) {
        uint4 z = make_uint4(0u,0u,0u,0u);
        g_h0[g] = z;
        g_baseh[g] = z;
    }
}

// error[mask] = onehot(y_true) - y_soft[mask]; last occurrence wins (mask sorted).
// Writes into SORTED space at inv[m]. Fused sigma (run-length weighted).
__global__ void k_scatter1(const float* __restrict__ y_soft,
                           const int* __restrict__ mask,
                           const int* __restrict__ y_true) {
    __shared__ float sh[256];
    int g = blockIdx.x*blockDim.x + threadIdx.x;
    float contrib = 0.f;
    if (g < NT*NC) {
        int i = g / NC, c = g - NC*i;
        int m = mask[i];
        bool last = (i == NT-1) || (mask[i+1] != m);
        if (last) {
            int p = g_inv[m];
            float err = ((c == y_true[i]) ? 1.0f : 0.0f) - y_soft[m*NC + c];
            ((__half*)g_h0)[p*NC + c]    = __float2half_rn(err * g_snorm[p]);
            ((__half*)g_baseh)[p*NC + c] = __float2half_rn((1.0f - ALPHA_C) * err);
            int r = 1, k = i;
            while (k > 0 && mask[k-1] == m) { r++; k--; }
            contrib = (float)r * fabsf(err);
        }
    }
    sh[threadIdx.x] = contrib;
    __syncthreads();
    for (int o = 128; o; o >>= 1) {
        if (threadIdx.x < o) sh[threadIdx.x] += sh[threadIdx.x + o];
        __syncthreads();
    }
    if (threadIdx.x == 0 && sh[0] != 0.f) atomicAdd(&g_sigma, (double)sh[0]);
}

// one propagation layer (sorted space, fp16 h + fp16 base)
// thread handles 8 classes: g in [0, NN*5), v=g/5 (sorted id), j=g%5
// If yout: writes fp32 rows; outmap (nullable) maps sorted->original row.
__global__ void k_prop(const uint4* __restrict__ hin,
                       uint4* __restrict__ hout,
                       float4* __restrict__ yout,
                       const int* __restrict__ outmap,
                       float alpha, float lo, float hi) {
    int g = blockIdx.x*blockDim.x + threadIdx.x;
    if (g >= NH4) return;
    int v = g / HJ;
    int j = g - v*HJ;
    int s = __ldg(&g_srowptr[v]);
    int e = __ldg(&g_srowptr[v+1]);
    float2 a0 = make_float2(0.f,0.f), a1 = a0, a2 = a0, a3 = a0;
    #pragma unroll 4
    for (int k = s; k < e; k++) {
        int u = __ldg(&g_scolidx[k]);
        uint4 t = __ldg(&hin[u*HJ + j]);
        float2 f;
        f = __half22float2(*reinterpret_cast<const __half2*>(&t.x)); a0.x += f.x; a0.y += f.y;
        f = __half22float2(*reinterpret_cast<const __half2*>(&t.y)); a1.x += f.x; a1.y += f.y;
        f = __half22float2(*reinterpret_cast<const __half2*>(&t.z)); a2.x += f.x; a2.y += f.y;
        f = __half22float2(*reinterpret_cast<const __half2*>(&t.w)); a3.x += f.x; a3.y += f.y;
    }
    float nv = __ldg(&g_snorm[v]);
    float a = alpha * nv;
    uint4 bh = __ldg(&g_baseh[g]);
    float2 b0 = __half22float2(*reinterpret_cast<const __half2*>(&bh.x));
    float2 b1 = __half22float2(*reinterpret_cast<const __half2*>(&bh.y));
    float2 b2 = __half22float2(*reinterpret_cast<const __half2*>(&bh.z));
    float2 b3 = __half22float2(*reinterpret_cast<const __half2*>(&bh.w));
    float y0 = fminf(fmaxf(fmaf(a, a0.x, b0.x), lo), hi);
    float y1 = fminf(fmaxf(fmaf(a, a0.y, b0.y), lo), hi);
    float y2 = fminf(fmaxf(fmaf(a, a1.x, b1.x), lo), hi);
    float y3 = fminf(fmaxf(fmaf(a, a1.y, b1.y), lo), hi);
    float y4 = fminf(fmaxf(fmaf(a, a2.x, b2.x), lo), hi);
    float y5 = fminf(fmaxf(fmaf(a, a2.y, b2.y), lo), hi);
    float y6 = fminf(fmaxf(fmaf(a, a3.x, b3.x), lo), hi);
    float y7 = fminf(fmaxf(fmaf(a, a3.y, b3.y), lo), hi);
    if (yout) {
        int ov = outmap ? __ldg(&outmap[v]) : v;
        yout[ov*CJ + j*2]     = make_float4(y0, y1, y2, y3);
        yout[ov*CJ + j*2 + 1] = make_float4(y4, y5, y6, y7);
    }
    if (hout) {
        __half2 h0 = __floats2half2_rn(y0*nv, y1*nv);
        __half2 h1 = __floats2half2_rn(y2*nv, y3*nv);
        __half2 h2 = __floats2half2_rn(y4*nv, y5*nv);
        __half2 h3 = __floats2half2_rn(y6*nv, y7*nv);
        uint4 o;
        o.x = *reinterpret_cast<unsigned*>(&h0);
        o.y = *reinterpret_cast<unsigned*>(&h1);
        o.z = *reinterpret_cast<unsigned*>(&h2);
        o.w = *reinterpret_cast<unsigned*>(&h3);
        hout[g] = o;
    }
}

__global__ void k_scale() {
    int v = blockIdx.x*blockDim.x + threadIdx.x;
    if (v >= NN) return;
    float denom = 0.f;
    #pragma unroll
    for (int j = 0; j < CJ; j++) {
        float4 t = g_y[v*CJ + j];
        denom += fabsf(t.x) + fabsf(t.y) + fabsf(t.z) + fabsf(t.w);
    }
    float sig = (float)g_sigma / (float)NT;
    float s = sig / denom;
    if (isinf(s) || s > 1000.0f) s = 1.0f;
    g_scalebuf[v] = s;
}

// y1 = y_soft[perm[v]] + scale*smoothed_error; emit h/base fp16 (sorted space)
__global__ void k_apply(const float* __restrict__ y_soft) {
    int g = blockIdx.x*blockDim.x + threadIdx.x;
    if (g >= NC4) return;
    int v = g / CJ;
    int jj = g - v*CJ;
    int ov = __ldg(&g_perm[v]);
    float s = g_scalebuf[v];
    float nv = g_snorm[v];
    float4 se = g_y[g];
    const float4* ysp = (const float4*)(y_soft + ov*NC) + jj;
    float4 ys = __ldg(ysp);
    float4 y1;
    y1.x = fmaf(s, se.x, ys.x);
    y1.y = fmaf(s, se.y, ys.y);
    y1.z = fmaf(s, se.z, ys.z);
    y1.w = fmaf(s, se.w, ys.w);
    __half2 p0 = __floats2half2_rn(y1.x*nv, y1.y*nv);
    __half2 p1 = __floats2half2_rn(y1.z*nv, y1.w*nv);
    uint2 hw;
    hw.x = *reinterpret_cast<unsigned*>(&p0);
    hw.y = *reinterpret_cast<unsigned*>(&p1);
    ((uint2*)g_h0)[g] = hw;
    const float oma = 1.0f - ALPHA_S;
    __half2 q0 = __floats2half2_rn(oma*y1.x, oma*y1.y);
    __half2 q1 = __floats2half2_rn(oma*y1.z, oma*y1.w);
    uint2 bw;
    bw.x = *reinterpret_cast<unsigned*>(&q0);
    bw.y = *reinterpret_cast<unsigned*>(&q1);
    ((uint2*)g_baseh)[g] = bw;
}

// y1[mask] = onehot(y_true), last occurrence wins; sorted space
__global__ void k_scatter2(const int* __restrict__ mask,
                           const int* __restrict__ y_true) {
    int g = blockIdx.x*blockDim.x + threadIdx.x;
    if (g >= NT*NC) return;
    int i = g / NC, c = g - NC*i;
    int m = mask[i];
    bool last = (i == NT-1) || (mask[i+1] != m);
    if (last) {
        int p = g_inv[m];
        float val = (c == y_true[i]) ? 1.0f : 0.0f;
        ((__half*)g_h0)[p*NC + c]    = __float2half_rn(val * g_snorm[p]);
        ((__half*)g_baseh)[p*NC + c] = __float2half_rn((1.0f - ALPHA_S) * val);
    }
}

extern "C" void kernel_launch(void* const* d_in, const int* in_sizes, int n_in,
                              void* d_out, int out_size) {
    const float* y_soft_f = (const float*)d_in[0];
    const int* src    = (const int*)d_in[1];
    const int* dst    = (const int*)d_in[2];
    const int* y_true = (const int*)d_in[3];
    const int* mask   = (const int*)d_in[4];

    uint4 *h0, *h1;
    float4 *yb;
    int *permp;
    cudaGetSymbolAddress((void**)&h0, g_h0);
    cudaGetSymbolAddress((void**)&h1, g_h1);
    cudaGetSymbolAddress((void**)&yb, g_y);
    cudaGetSymbolAddress((void**)&permp, g_perm);

    const int B = 256;
    const int GN  = (NN + B - 1) / B;
    const int GE  = (NE + B - 1) / B;
    const int G4  = (NC4 + B - 1) / B;
    const int GH  = (NH4 + B - 1) / B;
    const int GTC = (NT*NC + B - 1) / B;

    // ---- build degree-sorted permutation + CSR ----
    k_init<<<GN, B>>>();
    k_count<<<GE, B>>>(dst);
    k_hist<<<GN, B>>>();
    k_binscan<<<1, NBIN>>>();
    k_perm<<<GN, B>>>();
    k_scan1<<<SCAN_B, SCAN_T>>>();
    k_scan2<<<1, 128>>>();
    k_scan3<<<SCAN_B, SCAN_T>>>();
    k_fill<<<GE, B>>>(src, dst);

    // ---- correct phase ----
    k_zero2<<<GH, B>>>();
    k_scatter1<<<GTC, B>>>(y_soft_f, mask, y_true);
    for (int i = 0; i < 9; i++)
        k_prop<<<GH, B>>>((i & 1) ? h1 : h0, (i & 1) ? h0 : h1, nullptr, nullptr,
                          ALPHA_C, -1.0f, 1.0f);
    k_prop<<<GH, B>>>(h1, nullptr, yb, nullptr, ALPHA_C, -1.0f, 1.0f);  // -> g_y (sorted)

    // ---- scale + apply + re-mask ----
    k_scale<<<GN, B>>>();
    k_apply<<<G4, B>>>(y_soft_f);
    k_scatter2<<<GTC, B>>>(mask, y_true);

    // ---- smooth phase ----
    for (int i = 0; i < 9; i++)
        k_prop<<<GH, B>>>((i & 1) ? h1 : h0, (i & 1) ? h0 : h1, nullptr, nullptr,
                          ALPHA_S, 0.0f, 1.0f);
    k_prop<<<GH, B>>>(h1, nullptr, (float4*)d_out, permp, ALPHA_S, 0.0f, 1.0f);
}

// round 8
// speedup vs baseline: 1.0037x; 1.0037x over previous
#include <cuda_runtime.h>
#include <cuda_fp16.h>
#include <math.h>

#define NN 100000
#define NE 1600000
#define NC 40
#define CJ 10              // 40 floats = 10 float4 chunks (fp32 buffers)
#define HJ 5               // 40 halves = 5 uint4 chunks (fp16 buffers)
#define NT 50000
#define NC4 (NN*CJ)
#define NH4 (NN*HJ)
#define SCAN_T 1024
#define SCAN_B ((NN + SCAN_T - 1)/SCAN_T)
#define NBIN 256

#define ALPHA_C 0.979f
#define ALPHA_S 0.756f

// ---- scratch (static device globals: allocation-free) ----
static __device__ int    g_deg[NN];       // original-space degree
static __device__ int    g_perm[NN];      // sorted pos -> original id
static __device__ int    g_inv[NN];       // original id -> sorted pos
static __device__ int    g_sdeg[NN];      // sorted-space degree
static __device__ float  g_snorm[NN];     // sorted-space norm
static __device__ int    g_srowptr[NN+1];
static __device__ int    g_scursor[NN];
static __device__ int    g_scolidx[NE];   // sorted ids
static __device__ float  g_scalebuf[NN];
static __device__ uint4  g_h0[NH4];       // fp16 feature buffer (ping), sorted space
static __device__ uint4  g_h1[NH4];       // fp16 feature buffer (pong), sorted space
static __device__ uint4  g_baseh[NH4];    // fp16 (1-alpha)*y0 anchor, sorted space
static __device__ float4 g_y[NC4];        // smoothed_error (fp32), sorted space
static __device__ int    g_bins[NBIN];
static __device__ int    g_bincur[NBIN];
static __device__ int    g_bsum[SCAN_B];
static __device__ double g_sigma;

__global__ void k_init() {
    int v = blockIdx.x*blockDim.x + threadIdx.x;
    if (v < NN) g_deg[v] = 0;
    if (v < NBIN) g_bins[v] = 0;
    if (v == 0) g_sigma = 0.0;
}

__global__ void k_count(const int* __restrict__ dst) {
    int e = blockIdx.x*blockDim.x + threadIdx.x;
    if (e < NE) atomicAdd(&g_deg[dst[e]], 1);
}

__global__ void k_hist() {
    int v = blockIdx.x*blockDim.x + threadIdx.x;
    if (v < NN) {
        int b = g_deg[v]; if (b > NBIN-1) b = NBIN-1;
        atomicAdd(&g_bins[b], 1);
    }
}

// exclusive scan of g_bins[256], one block of 256; also seeds g_bincur
__global__ void k_binscan() {
    __shared__ int wsum[8];
    int t = threadIdx.x;
    int lane = t & 31, w = t >> 5;
    int val = g_bins[t];
    int inc = val;
    #pragma unroll
    for (int o = 1; o < 32; o <<= 1) {
        int x = __shfl_up_sync(0xffffffffu, inc, o);
        if (lane >= o) inc += x;
    }
    if (lane == 31) wsum[w] = inc;
    __syncthreads();
    if (t == 0) {
        int r = 0;
        #pragma unroll
        for (int i = 0; i < 8; i++) { int x = wsum[i]; wsum[i] = r; r += x; }
    }
    __syncthreads();
    int ex = inc - val + wsum[w];
    g_bincur[t] = ex;
}

// scatter nodes into degree-sorted order; build perm/inv/sdeg/snorm
__global__ void k_perm() {
    int v = blockIdx.x*blockDim.x + threadIdx.x;
    if (v >= NN) return;
    int d = g_deg[v];
    int b = d > NBIN-1 ? NBIN-1 : d;
    int p = atomicAdd(&g_bincur[b], 1);
    g_perm[p] = v;
    g_inv[v] = p;
    g_sdeg[p] = d;
    g_snorm[p] = 1.0f / sqrtf((float)(d > 0 ? d : 1));
}

__global__ void k_scan1() {
    __shared__ int sh[32];
    int v = blockIdx.x*SCAN_T + threadIdx.x;
    int d = (v < NN) ? g_sdeg[v] : 0;
    int s = d;
    #pragma unroll
    for (int o = 16; o; o >>= 1) s += __shfl_down_sync(0xffffffffu, s, o);
    if ((threadIdx.x & 31) == 0) sh[threadIdx.x >> 5] = s;
    __syncthreads();
    if (threadIdx.x < 32) {
        int t = sh[threadIdx.x];
        #pragma unroll
        for (int o = 16; o; o >>= 1) t += __shfl_down_sync(0xffffffffu, t, o);
        if (threadIdx.x == 0) g_bsum[blockIdx.x] = t;
    }
}

// parallel exclusive scan of g_bsum[SCAN_B] (SCAN_B=98 <= 128), one block of 128
__global__ void k_scan2() {
    __shared__ int wsum[4];
    int t = threadIdx.x;
    int lane = t & 31, w = t >> 5;
    int val = (t < SCAN_B) ? g_bsum[t] : 0;
    int inc = val;
    #pragma unroll
    for (int o = 1; o < 32; o <<= 1) {
        int x = __shfl_up_sync(0xffffffffu, inc, o);
        if (lane >= o) inc += x;
    }
    if (lane == 31) wsum[w] = inc;
    __syncthreads();
    if (t == 0) {
        int r = 0;
        #pragma unroll
        for (int i = 0; i < 4; i++) { int x = wsum[i]; wsum[i] = r; r += x; }
    }
    __syncthreads();
    if (t < SCAN_B) g_bsum[t] = inc - val + wsum[w];   // exclusive
}

__global__ void k_scan3() {
    __shared__ int wsum[32];
    int v = blockIdx.x*SCAN_T + threadIdx.x;
    int d = (v < NN) ? g_sdeg[v] : 0;
    int lane = threadIdx.x & 31, w = threadIdx.x >> 5;
    int inc = d;
    #pragma unroll
    for (int o = 1; o < 32; o <<= 1) {
        int t = __shfl_up_sync(0xffffffffu, inc, o);
        if (lane >= o) inc += t;
    }
    if (lane == 31) wsum[w] = inc;
    __syncthreads();
    if (w == 0) {
        int t = wsum[lane];
        int ti = t;
        #pragma unroll
        for (int o = 1; o < 32; o <<= 1) {
            int x = __shfl_up_sync(0xffffffffu, ti, o);
            if (lane >= o) ti += x;
        }
        wsum[lane] = ti - t;   // exclusive
    }
    __syncthreads();
    int ex = inc - d + wsum[w] + g_bsum[blockIdx.x];
    if (v < NN) {
        g_srowptr[v] = ex;
        g_scursor[v] = ex;
        if (v == NN-1) g_srowptr[NN] = ex + d;
    }
}

// fill sorted CSR: edges land in row inv[dst], storing sorted src ids
__global__ void k_fill(const int* __restrict__ src, const int* __restrict__ dst) {
    int e = blockIdx.x*blockDim.x + threadIdx.x;
    if (e < NE) {
        int p = g_inv[dst[e]];
        int pos = atomicAdd(&g_scursor[p], 1);
        g_scolidx[pos] = g_inv[src[e]];
    }
}

__global__ void k_zero2() {
    int g = blockIdx.x*blockDim.x + threadIdx.x;
    if (g < NH4) {
        uint4 z = make_uint4(0u,0u,0u,0u);
        g_h0[g] = z;
        g_baseh[g] = z;
    }
}

// error[mask] = onehot(y_true) - y_soft[mask]; last occurrence wins (mask sorted).
// Writes into SORTED space at inv[m]. Fused sigma (run-length weighted).
__global__ void k_scatter1(const float* __restrict__ y_soft,
                           const int* __restrict__ mask,
                           const int* __restrict__ y_true) {
    __shared__ float sh[256];
    int g = blockIdx.x*blockDim.x + threadIdx.x;
    float contrib = 0.f;
    if (g < NT*NC) {
        int i = g / NC, c = g - NC*i;
        int m = mask[i];
        bool last = (i == NT-1) || (mask[i+1] != m);
        if (last) {
            int p = g_inv[m];
            float err = ((c == y_true[i]) ? 1.0f : 0.0f) - y_soft[m*NC + c];
            ((__half*)g_h0)[p*NC + c]    = __float2half_rn(err * g_snorm[p]);
            ((__half*)g_baseh)[p*NC + c] = __float2half_rn((1.0f - ALPHA_C) * err);
            int r = 1, k = i;
            while (k > 0 && mask[k-1] == m) { r++; k--; }
            contrib = (float)r * fabsf(err);
        }
    }
    sh[threadIdx.x] = contrib;
    __syncthreads();
    for (int o = 128; o; o >>= 1) {
        if (threadIdx.x < o) sh[threadIdx.x] += sh[threadIdx.x + o];
        __syncthreads();
    }
    if (threadIdx.x == 0 && sh[0] != 0.f) atomicAdd(&g_sigma, (double)sh[0]);
}

// one propagation layer (sorted space, fp16 h + fp16 base)
// thread handles 8 classes: g in [0, NN*5), v=g/5 (sorted id), j=g%5
// If yout: writes fp32 rows; outmap (nullable) maps sorted->original row.
__global__ void k_prop(const uint4* __restrict__ hin,
                       uint4* __restrict__ hout,
                       float4* __restrict__ yout,
                       const int* __restrict__ outmap,
                       float alpha, float lo, float hi) {
    int g = blockIdx.x*blockDim.x + threadIdx.x;
    if (g >= NH4) return;
    int v = g / HJ;
    int j = g - v*HJ;
    int s = __ldg(&g_srowptr[v]);
    int e = __ldg(&g_srowptr[v+1]);
    float2 a0 = make_float2(0.f,0.f), a1 = a0, a2 = a0, a3 = a0;
    #pragma unroll 4
    for (int k = s; k < e; k++) {
        int u = __ldg(&g_scolidx[k]);
        uint4 t = __ldg(&hin[u*HJ + j]);
        float2 f;
        f = __half22float2(*reinterpret_cast<const __half2*>(&t.x)); a0.x += f.x; a0.y += f.y;
        f = __half22float2(*reinterpret_cast<const __half2*>(&t.y)); a1.x += f.x; a1.y += f.y;
        f = __half22float2(*reinterpret_cast<const __half2*>(&t.z)); a2.x += f.x; a2.y += f.y;
        f = __half22float2(*reinterpret_cast<const __half2*>(&t.w)); a3.x += f.x; a3.y += f.y;
    }
    float nv = __ldg(&g_snorm[v]);
    float a = alpha * nv;
    uint4 bh = __ldg(&g_baseh[g]);
    float2 b0 = __half22float2(*reinterpret_cast<const __half2*>(&bh.x));
    float2 b1 = __half22float2(*reinterpret_cast<const __half2*>(&bh.y));
    float2 b2 = __half22float2(*reinterpret_cast<const __half2*>(&bh.z));
    float2 b3 = __half22float2(*reinterpret_cast<const __half2*>(&bh.w));
    float y0 = fminf(fmaxf(fmaf(a, a0.x, b0.x), lo), hi);
    float y1 = fminf(fmaxf(fmaf(a, a0.y, b0.y), lo), hi);
    float y2 = fminf(fmaxf(fmaf(a, a1.x, b1.x), lo), hi);
    float y3 = fminf(fmaxf(fmaf(a, a1.y, b1.y), lo), hi);
    float y4 = fminf(fmaxf(fmaf(a, a2.x, b2.x), lo), hi);
    float y5 = fminf(fmaxf(fmaf(a, a2.y, b2.y), lo), hi);
    float y6 = fminf(fmaxf(fmaf(a, a3.x, b3.x), lo), hi);
    float y7 = fminf(fmaxf(fmaf(a, a3.y, b3.y), lo), hi);
    if (yout) {
        int ov = outmap ? __ldg(&outmap[v]) : v;
        yout[ov*CJ + j*2]     = make_float4(y0, y1, y2, y3);
        yout[ov*CJ + j*2 + 1] = make_float4(y4, y5, y6, y7);
    }
    if (hout) {
        __half2 h0 = __floats2half2_rn(y0*nv, y1*nv);
        __half2 h1 = __floats2half2_rn(y2*nv, y3*nv);
        __half2 h2 = __floats2half2_rn(y4*nv, y5*nv);
        __half2 h3 = __floats2half2_rn(y6*nv, y7*nv);
        uint4 o;
        o.x = *reinterpret_cast<unsigned*>(&h0);
        o.y = *reinterpret_cast<unsigned*>(&h1);
        o.z = *reinterpret_cast<unsigned*>(&h2);
        o.w = *reinterpret_cast<unsigned*>(&h3);
        hout[g] = o;
    }
}

__global__ void k_scale() {
    int v = blockIdx.x*blockDim.x + threadIdx.x;
    if (v >= NN) return;
    float denom = 0.f;
    #pragma unroll
    for (int j = 0; j < CJ; j++) {
        float4 t = g_y[v*CJ + j];
        denom += fabsf(t.x) + fabsf(t.y) + fabsf(t.z) + fabsf(t.w);
    }
    float sig = (float)g_sigma / (float)NT;
    float s = sig / denom;
    if (isinf(s) || s > 1000.0f) s = 1.0f;
    g_scalebuf[v] = s;
}

// y1 = y_soft[perm[v]] + scale*smoothed_error; emit h/base fp16 (sorted space)
__global__ void k_apply(const float* __restrict__ y_soft) {
    int g = blockIdx.x*blockDim.x + threadIdx.x;
    if (g >= NC4) return;
    int v = g / CJ;
    int jj = g - v*CJ;
    int ov = __ldg(&g_perm[v]);
    float s = g_scalebuf[v];
    float nv = g_snorm[v];
    float4 se = g_y[g];
    const float4* ysp = (const float4*)(y_soft + ov*NC) + jj;
    float4 ys = __ldg(ysp);
    float4 y1;
    y1.x = fmaf(s, se.x, ys.x);
    y1.y = fmaf(s, se.y, ys.y);
    y1.z = fmaf(s, se.z, ys.z);
    y1.w = fmaf(s, se.w, ys.w);
    __half2 p0 = __floats2half2_rn(y1.x*nv, y1.y*nv);
    __half2 p1 = __floats2half2_rn(y1.z*nv, y1.w*nv);
    uint2 hw;
    hw.x = *reinterpret_cast<unsigned*>(&p0);
    hw.y = *reinterpret_cast<unsigned*>(&p1);
    ((uint2*)g_h0)[g] = hw;
    const float oma = 1.0f - ALPHA_S;
    __half2 q0 = __floats2half2_rn(oma*y1.x, oma*y1.y);
    __half2 q1 = __floats2half2_rn(oma*y1.z, oma*y1.w);
    uint2 bw;
    bw.x = *reinterpret_cast<unsigned*>(&q0);
    bw.y = *reinterpret_cast<unsigned*>(&q1);
    ((uint2*)g_baseh)[g] = bw;
}

// y1[mask] = onehot(y_true), last occurrence wins; sorted space
__global__ void k_scatter2(const int* __restrict__ mask,
                           const int* __restrict__ y_true) {
    int g = blockIdx.x*blockDim.x + threadIdx.x;
    if (g >= NT*NC) return;
    int i = g / NC, c = g - NC*i;
    int m = mask[i];
    bool last = (i == NT-1) || (mask[i+1] != m);
    if (last) {
        int p = g_inv[m];
        float val = (c == y_true[i]) ? 1.0f : 0.0f;
        ((__half*)g_h0)[p*NC + c]    = __float2half_rn(val * g_snorm[p]);
        ((__half*)g_baseh)[p*NC + c] = __float2half_rn((1.0f - ALPHA_S) * val);
    }
}

extern "C" void kernel_launch(void* const* d_in, const int* in_sizes, int n_in,
                              void* d_out, int out_size) {
    const float* y_soft_f = (const float*)d_in[0];
    const int* src    = (const int*)d_in[1];
    const int* dst    = (const int*)d_in[2];
    const int* y_true = (const int*)d_in[3];
    const int* mask   = (const int*)d_in[4];

    uint4 *h0, *h1;
    float4 *yb;
    int *permp;
    cudaGetSymbolAddress((void**)&h0, g_h0);
    cudaGetSymbolAddress((void**)&h1, g_h1);
    cudaGetSymbolAddress((void**)&yb, g_y);
    cudaGetSymbolAddress((void**)&permp, g_perm);

    const int B = 256;
    const int GN  = (NN + B - 1) / B;
    const int GE  = (NE + B - 1) / B;
    const int G4  = (NC4 + B - 1) / B;
    const int GH  = (NH4 + B - 1) / B;
    const int GTC = (NT*NC + B - 1) / B;

    // ---- build degree-sorted permutation + CSR ----
    k_init<<<GN, B>>>();
    k_count<<<GE, B>>>(dst);
    k_hist<<<GN, B>>>();
    k_binscan<<<1, NBIN>>>();
    k_perm<<<GN, B>>>();
    k_scan1<<<SCAN_B, SCAN_T>>>();
    k_scan2<<<1, 128>>>();
    k_scan3<<<SCAN_B, SCAN_T>>>();
    k_fill<<<GE, B>>>(src, dst);

    // ---- correct phase ----
    k_zero2<<<GH, B>>>();
    k_scatter1<<<GTC, B>>>(y_soft_f, mask, y_true);
    for (int i = 0; i < 9; i++)
        k_prop<<<GH, B>>>((i & 1) ? h1 : h0, (i & 1) ? h0 : h1, nullptr, nullptr,
                          ALPHA_C, -1.0f, 1.0f);
    k_prop<<<GH, B>>>(h1, nullptr, yb, nullptr, ALPHA_C, -1.0f, 1.0f);  // -> g_y (sorted)

    // ---- scale + apply + re-mask ----
    k_scale<<<GN, B>>>();
    k_apply<<<G4, B>>>(y_soft_f);
    k_scatter2<<<GTC, B>>>(mask, y_true);

    // ---- smooth phase ----
    for (int i = 0; i < 9; i++)
        k_prop<<<GH, B>>>((i & 1) ? h1 : h0, (i & 1) ? h0 : h1, nullptr, nullptr,
                          ALPHA_S, 0.0f, 1.0f);
    k_prop<<<GH, B>>>(h1, nullptr, (float4*)d_out, permp, ALPHA_S, 0.0f, 1.0f);
}

// round 9
// speedup vs baseline: 1.0892x; 1.0852x over previous
#include <cuda_runtime.h>
#include <cuda_fp16.h>
#include <math.h>

#define NN 100000
#define NE 1600000
#define NC 40
#define CJ 10              // 40 floats = 10 float4 chunks (fp32 buffers)
#define HJ 5               // 40 halves = 5 uint4 chunks (fp16 buffers)
#define NT 50000
#define NC4 (NN*CJ)
#define NH4 (NN*HJ)
#define SCAN_T 1024
#define SCAN_B ((NN + SCAN_T - 1)/SCAN_T)
#define NBIN 256

#define ALPHA_C 0.979f
#define ALPHA_S 0.756f

// ---- scratch (static device globals: allocation-free) ----
static __device__ int    g_deg[NN];       // original-space degree
static __device__ int    g_perm[NN];      // sorted pos -> original id
static __device__ int    g_inv[NN];       // original id -> sorted pos
static __device__ int    g_sdeg[NN];      // sorted-space degree
static __device__ float  g_snorm[NN];     // sorted-space norm
static __device__ int    g_srowptr[NN+1];
static __device__ int    g_scursor[NN];
static __device__ int    g_scolidx[NE];   // sorted ids
static __device__ float  g_scalebuf[NN];
static __device__ uint4  g_h0[NH4];       // fp16 feature buffer (ping), sorted space
static __device__ uint4  g_h1[NH4];       // fp16 feature buffer (pong), sorted space
static __device__ uint4  g_baseh[NH4];    // fp16 (1-alpha)*y0 anchor, sorted space
static __device__ float4 g_y[NC4];        // smoothed_error (fp32), sorted space
static __device__ int    g_bins[NBIN];
static __device__ int    g_bincur[NBIN];
static __device__ int    g_bsum[SCAN_B];
static __device__ double g_sigma;

__global__ void k_init() {
    int v = blockIdx.x*blockDim.x + threadIdx.x;
    if (v < NN) g_deg[v] = 0;
    if (v < NBIN) g_bins[v] = 0;
    if (v == 0) g_sigma = 0.0;
}

__global__ void k_count(const int* __restrict__ dst) {
    int e = blockIdx.x*blockDim.x + threadIdx.x;
    if (e < NE) atomicAdd(&g_deg[dst[e]], 1);
}

__global__ void k_hist() {
    int v = blockIdx.x*blockDim.x + threadIdx.x;
    if (v < NN) {
        int b = g_deg[v]; if (b > NBIN-1) b = NBIN-1;
        atomicAdd(&g_bins[b], 1);
    }
}

// exclusive scan of g_bins[256], one block of 256; also seeds g_bincur
__global__ void k_binscan() {
    __shared__ int wsum[8];
    int t = threadIdx.x;
    int lane = t & 31, w = t >> 5;
    int val = g_bins[t];
    int inc = val;
    #pragma unroll
    for (int o = 1; o < 32; o <<= 1) {
        int x = __shfl_up_sync(0xffffffffu, inc, o);
        if (lane >= o) inc += x;
    }
    if (lane == 31) wsum[w] = inc;
    __syncthreads();
    if (t == 0) {
        int r = 0;
        #pragma unroll
        for (int i = 0; i < 8; i++) { int x = wsum[i]; wsum[i] = r; r += x; }
    }
    __syncthreads();
    int ex = inc - val + wsum[w];
    g_bincur[t] = ex;
}

// scatter nodes into degree-sorted order; build perm/inv/sdeg/snorm
__global__ void k_perm() {
    int v = blockIdx.x*blockDim.x + threadIdx.x;
    if (v >= NN) return;
    int d = g_deg[v];
    int b = d > NBIN-1 ? NBIN-1 : d;
    int p = atomicAdd(&g_bincur[b], 1);
    g_perm[p] = v;
    g_inv[v] = p;
    g_sdeg[p] = d;
    g_snorm[p] = 1.0f / sqrtf((float)(d > 0 ? d : 1));
}

__global__ void k_scan1() {
    __shared__ int sh[32];
    int v = blockIdx.x*SCAN_T + threadIdx.x;
    int d = (v < NN) ? g_sdeg[v] : 0;
    int s = d;
    #pragma unroll
    for (int o = 16; o; o >>= 1) s += __shfl_down_sync(0xffffffffu, s, o);
    if ((threadIdx.x & 31) == 0) sh[threadIdx.x >> 5] = s;
    __syncthreads();
    if (threadIdx.x < 32) {
        int t = sh[threadIdx.x];
        #pragma unroll
        for (int o = 16; o; o >>= 1) t += __shfl_down_sync(0xffffffffu, t, o);
        if (threadIdx.x == 0) g_bsum[blockIdx.x] = t;
    }
}

// parallel exclusive scan of g_bsum[SCAN_B] (SCAN_B=98 <= 128), one block of 128
__global__ void k_scan2() {
    __shared__ int wsum[4];
    int t = threadIdx.x;
    int lane = t & 31, w = t >> 5;
    int val = (t < SCAN_B) ? g_bsum[t] : 0;
    int inc = val;
    #pragma unroll
    for (int o = 1; o < 32; o <<= 1) {
        int x = __shfl_up_sync(0xffffffffu, inc, o);
        if (lane >= o) inc += x;
    }
    if (lane == 31) wsum[w] = inc;
    __syncthreads();
    if (t == 0) {
        int r = 0;
        #pragma unroll
        for (int i = 0; i < 4; i++) { int x = wsum[i]; wsum[i] = r; r += x; }
    }
    __syncthreads();
    if (t < SCAN_B) g_bsum[t] = inc - val + wsum[w];   // exclusive
}

__global__ void k_scan3() {
    __shared__ int wsum[32];
    int v = blockIdx.x*SCAN_T + threadIdx.x;
    int d = (v < NN) ? g_sdeg[v] : 0;
    int lane = threadIdx.x & 31, w = threadIdx.x >> 5;
    int inc = d;
    #pragma unroll
    for (int o = 1; o < 32; o <<= 1) {
        int t = __shfl_up_sync(0xffffffffu, inc, o);
        if (lane >= o) inc += t;
    }
    if (lane == 31) wsum[w] = inc;
    __syncthreads();
    if (w == 0) {
        int t = wsum[lane];
        int ti = t;
        #pragma unroll
        for (int o = 1; o < 32; o <<= 1) {
            int x = __shfl_up_sync(0xffffffffu, ti, o);
            if (lane >= o) ti += x;
        }
        wsum[lane] = ti - t;   // exclusive
    }
    __syncthreads();
    int ex = inc - d + wsum[w] + g_bsum[blockIdx.x];
    if (v < NN) {
        g_srowptr[v] = ex;
        g_scursor[v] = ex;
        if (v == NN-1) g_srowptr[NN] = ex + d;
    }
}

// fill sorted CSR: edges land in row inv[dst], storing sorted src ids
__global__ void k_fill(const int* __restrict__ src, const int* __restrict__ dst) {
    int e = blockIdx.x*blockDim.x + threadIdx.x;
    if (e < NE) {
        int p = g_inv[dst[e]];
        int pos = atomicAdd(&g_scursor[p], 1);
        g_scolidx[pos] = g_inv[src[e]];
    }
}

__global__ void k_zero2() {
    int g = blockIdx.x*blockDim.x + threadIdx.x;
    if (g < NH4) {
        uint4 z = make_uint4(0u,0u,0u,0u);
        g_h0[g] = z;
        g_baseh[g] = z;
    }
}

// error[mask] = onehot(y_true) - y_soft[mask]; last occurrence wins (mask sorted).
// Writes into SORTED space at inv[m]. Fused sigma (run-length weighted).
__global__ void k_scatter1(const float* __restrict__ y_soft,
                           const int* __restrict__ mask,
                           const int* __restrict__ y_true) {
    __shared__ float sh[256];
    int g = blockIdx.x*blockDim.x + threadIdx.x;
    float contrib = 0.f;
    if (g < NT*NC) {
        int i = g / NC, c = g - NC*i;
        int m = mask[i];
        bool last = (i == NT-1) || (mask[i+1] != m);
        if (last) {
            int p = g_inv[m];
            float err = ((c == y_true[i]) ? 1.0f : 0.0f) - y_soft[m*NC + c];
            ((__half*)g_h0)[p*NC + c]    = __float2half_rn(err * g_snorm[p]);
            ((__half*)g_baseh)[p*NC + c] = __float2half_rn((1.0f - ALPHA_C) * err);
            int r = 1, k = i;
            while (k > 0 && mask[k-1] == m) { r++; k--; }
            contrib = (float)r * fabsf(err);
        }
    }
    sh[threadIdx.x] = contrib;
    __syncthreads();
    for (int o = 128; o; o >>= 1) {
        if (threadIdx.x < o) sh[threadIdx.x] += sh[threadIdx.x + o];
        __syncthreads();
    }
    if (threadIdx.x == 0 && sh[0] != 0.f) atomicAdd(&g_sigma, (double)sh[0]);
}

// one propagation layer (sorted space, fp16 h + fp16 base)
// LPT order: gid 0 maps to the HIGHEST-degree end (g = NH4-1-gid), so the
// heaviest blocks launch first and light blocks pack in behind.
__global__ void k_prop(const uint4* __restrict__ hin,
                       uint4* __restrict__ hout,
                       float4* __restrict__ yout,
                       const int* __restrict__ outmap,
                       float alpha, float lo, float hi) {
    int gid = blockIdx.x*blockDim.x + threadIdx.x;
    if (gid >= NH4) return;
    int g = NH4 - 1 - gid;          // descending degree order (LPT)
    int v = g / HJ;
    int j = g - v*HJ;
    int s = __ldg(&g_srowptr[v]);
    int e = __ldg(&g_srowptr[v+1]);
    float2 a0 = make_float2(0.f,0.f), a1 = a0, a2 = a0, a3 = a0;
    #pragma unroll 4
    for (int k = s; k < e; k++) {
        int u = __ldg(&g_scolidx[k]);
        uint4 t = __ldg(&hin[u*HJ + j]);
        float2 f;
        f = __half22float2(*reinterpret_cast<const __half2*>(&t.x)); a0.x += f.x; a0.y += f.y;
        f = __half22float2(*reinterpret_cast<const __half2*>(&t.y)); a1.x += f.x; a1.y += f.y;
        f = __half22float2(*reinterpret_cast<const __half2*>(&t.z)); a2.x += f.x; a2.y += f.y;
        f = __half22float2(*reinterpret_cast<const __half2*>(&t.w)); a3.x += f.x; a3.y += f.y;
    }
    float nv = __ldg(&g_snorm[v]);
    float a = alpha * nv;
    uint4 bh = __ldg(&g_baseh[g]);
    float2 b0 = __half22float2(*reinterpret_cast<const __half2*>(&bh.x));
    float2 b1 = __half22float2(*reinterpret_cast<const __half2*>(&bh.y));
    float2 b2 = __half22float2(*reinterpret_cast<const __half2*>(&bh.z));
    float2 b3 = __half22float2(*reinterpret_cast<const __half2*>(&bh.w));
    float y0 = fminf(fmaxf(fmaf(a, a0.x, b0.x), lo), hi);
    float y1 = fminf(fmaxf(fmaf(a, a0.y, b0.y), lo), hi);
    float y2 = fminf(fmaxf(fmaf(a, a1.x, b1.x), lo), hi);
    float y3 = fminf(fmaxf(fmaf(a, a1.y, b1.y), lo), hi);
    float y4 = fminf(fmaxf(fmaf(a, a2.x, b2.x), lo), hi);
    float y5 = fminf(fmaxf(fmaf(a, a2.y, b2.y), lo), hi);
    float y6 = fminf(fmaxf(fmaf(a, a3.x, b3.x), lo), hi);
    float y7 = fminf(fmaxf(fmaf(a, a3.y, b3.y), lo), hi);
    if (yout) {
        int ov = outmap ? __ldg(&outmap[v]) : v;
        yout[ov*CJ + j*2]     = make_float4(y0, y1, y2, y3);
        yout[ov*CJ + j*2 + 1] = make_float4(y4, y5, y6, y7);
    }
    if (hout) {
        __half2 h0 = __floats2half2_rn(y0*nv, y1*nv);
        __half2 h1 = __floats2half2_rn(y2*nv, y3*nv);
        __half2 h2 = __floats2half2_rn(y4*nv, y5*nv);
        __half2 h3 = __floats2half2_rn(y6*nv, y7*nv);
        uint4 o;
        o.x = *reinterpret_cast<unsigned*>(&h0);
        o.y = *reinterpret_cast<unsigned*>(&h1);
        o.z = *reinterpret_cast<unsigned*>(&h2);
        o.w = *reinterpret_cast<unsigned*>(&h3);
        hout[g] = o;
    }
}

__global__ void k_scale() {
    int v = blockIdx.x*blockDim.x + threadIdx.x;
    if (v >= NN) return;
    float denom = 0.f;
    #pragma unroll
    for (int j = 0; j < CJ; j++) {
        float4 t = g_y[v*CJ + j];
        denom += fabsf(t.x) + fabsf(t.y) + fabsf(t.z) + fabsf(t.w);
    }
    float sig = (float)g_sigma / (float)NT;
    float s = sig / denom;
    if (isinf(s) || s > 1000.0f) s = 1.0f;
    g_scalebuf[v] = s;
}

// y1 = y_soft[perm[v]] + scale*smoothed_error; emit h/base fp16 (sorted space)
__global__ void k_apply(const float* __restrict__ y_soft) {
    int g = blockIdx.x*blockDim.x + threadIdx.x;
    if (g >= NC4) return;
    int v = g / CJ;
    int jj = g - v*CJ;
    int ov = __ldg(&g_perm[v]);
    float s = g_scalebuf[v];
    float nv = g_snorm[v];
    float4 se = g_y[g];
    const float4* ysp = (const float4*)(y_soft + ov*NC) + jj;
    float4 ys = __ldg(ysp);
    float4 y1;
    y1.x = fmaf(s, se.x, ys.x);
    y1.y = fmaf(s, se.y, ys.y);
    y1.z = fmaf(s, se.z, ys.z);
    y1.w = fmaf(s, se.w, ys.w);
    __half2 p0 = __floats2half2_rn(y1.x*nv, y1.y*nv);
    __half2 p1 = __floats2half2_rn(y1.z*nv, y1.w*nv);
    uint2 hw;
    hw.x = *reinterpret_cast<unsigned*>(&p0);
    hw.y = *reinterpret_cast<unsigned*>(&p1);
    ((uint2*)g_h0)[g] = hw;
    const float oma = 1.0f - ALPHA_S;
    __half2 q0 = __floats2half2_rn(oma*y1.x, oma*y1.y);
    __half2 q1 = __floats2half2_rn(oma*y1.z, oma*y1.w);
    uint2 bw;
    bw.x = *reinterpret_cast<unsigned*>(&q0);
    bw.y = *reinterpret_cast<unsigned*>(&q1);
    ((uint2*)g_baseh)[g] = bw;
}

// y1[mask] = onehot(y_true), last occurrence wins; sorted space
__global__ void k_scatter2(const int* __restrict__ mask,
                           const int* __restrict__ y_true) {
    int g = blockIdx.x*blockDim.x + threadIdx.x;
    if (g >= NT*NC) return;
    int i = g / NC, c = g - NC*i;
    int m = mask[i];
    bool last = (i == NT-1) || (mask[i+1] != m);
    if (last) {
        int p = g_inv[m];
        float val = (c == y_true[i]) ? 1.0f : 0.0f;
        ((__half*)g_h0)[p*NC + c]    = __float2half_rn(val * g_snorm[p]);
        ((__half*)g_baseh)[p*NC + c] = __float2half_rn((1.0f - ALPHA_S) * val);
    }
}

extern "C" void kernel_launch(void* const* d_in, const int* in_sizes, int n_in,
                              void* d_out, int out_size) {
    const float* y_soft_f = (const float*)d_in[0];
    const int* src    = (const int*)d_in[1];
    const int* dst    = (const int*)d_in[2];
    const int* y_true = (const int*)d_in[3];
    const int* mask   = (const int*)d_in[4];

    uint4 *h0, *h1;
    float4 *yb;
    int *permp;
    cudaGetSymbolAddress((void**)&h0, g_h0);
    cudaGetSymbolAddress((void**)&h1, g_h1);
    cudaGetSymbolAddress((void**)&yb, g_y);
    cudaGetSymbolAddress((void**)&permp, g_perm);

    const int B = 256;
    const int GN  = (NN + B - 1) / B;
    const int GE  = (NE + B - 1) / B;
    const int G4  = (NC4 + B - 1) / B;
    const int GH  = (NH4 + B - 1) / B;
    const int GTC = (NT*NC + B - 1) / B;

    // ---- build degree-sorted permutation + CSR ----
    k_init<<<GN, B>>>();
    k_count<<<GE, B>>>(dst);
    k_hist<<<GN, B>>>();
    k_binscan<<<1, NBIN>>>();
    k_perm<<<GN, B>>>();
    k_scan1<<<SCAN_B, SCAN_T>>>();
    k_scan2<<<1, 128>>>();
    k_scan3<<<SCAN_B, SCAN_T>>>();
    k_fill<<<GE, B>>>(src, dst);

    // ---- correct phase ----
    k_zero2<<<GH, B>>>();
    k_scatter1<<<GTC, B>>>(y_soft_f, mask, y_true);
    for (int i = 0; i < 9; i++)
        k_prop<<<GH, B>>>((i & 1) ? h1 : h0, (i & 1) ? h0 : h1, nullptr, nullptr,
                          ALPHA_C, -1.0f, 1.0f);
    k_prop<<<GH, B>>>(h1, nullptr, yb, nullptr, ALPHA_C, -1.0f, 1.0f);  // -> g_y (sorted)

    // ---- scale + apply + re-mask ----
    k_scale<<<GN, B>>>();
    k_apply<<<G4, B>>>(y_soft_f);
    k_scatter2<<<GTC, B>>>(mask, y_true);

    // ---- smooth phase ----
    for (int i = 0; i < 9; i++)
        k_prop<<<GH, B>>>((i & 1) ? h1 : h0, (i & 1) ? h0 : h1, nullptr, nullptr,
                          ALPHA_S, 0.0f, 1.0f);
    k_prop<<<GH, B>>>(h1, nullptr, (float4*)d_out, permp, ALPHA_S, 0.0f, 1.0f);
}

// round 10
// speedup vs baseline: 1.1289x; 1.0365x over previous
#include <cuda_runtime.h>
#include <cuda_fp16.h>
#include <math.h>

#define NN 100000
#define NE 1600000
#define NC 40
#define CJ 10              // 40 floats = 10 float4 chunks (fp32 buffers)
#define HJ 5               // 40 halves = 5 uint4 chunks (fp16 buffers)
#define NT 50000
#define NC4 (NN*CJ)
#define NH4 (NN*HJ)
#define NBIN 1024

#define ALPHA_C 0.979f
#define ALPHA_S 0.756f

// ---- scratch (static device globals: allocation-free) ----
static __device__ int    g_deg[NN];       // original-space degree
static __device__ int    g_perm[NN];      // sorted pos -> original id
static __device__ int    g_inv[NN];       // original id -> sorted pos
static __device__ float  g_snorm[NN];     // sorted-space norm
static __device__ int    g_srowptr[NN+1];
static __device__ int    g_scursor[NN];
static __device__ int    g_scolidx[NE];   // sorted ids
static __device__ int    g_labmask[NN];   // sorted space: 0 = unmasked, else y_true+1
static __device__ uint4  g_h0[NH4];       // fp16 feature buffer (ping), sorted space
static __device__ uint4  g_h1[NH4];       // fp16 feature buffer (pong), sorted space
static __device__ uint4  g_baseh[NH4];    // fp16 (1-alpha)*y0 anchor, sorted space
static __device__ float4 g_y[NC4];        // smoothed_error (fp32), sorted space
static __device__ int    g_bins[NBIN];
static __device__ int    g_bincur[NBIN];  // mutable node cursor per bin
static __device__ int    g_binnode[NBIN]; // node-exclusive prefix per bin
static __device__ int    g_binedge[NBIN]; // edge-exclusive prefix per bin
static __device__ double g_sigma;

__global__ void k_init() {
    int v = blockIdx.x*blockDim.x + threadIdx.x;
    if (v < NN) { g_deg[v] = 0; g_labmask[v] = 0; }
    if (v < NBIN) g_bins[v] = 0;
    if (v == 0) g_sigma = 0.0;
}

// count in-degree, 4 edges per thread
__global__ void k_count(const int4* __restrict__ dst4) {
    int e = blockIdx.x*blockDim.x + threadIdx.x;
    if (e < NE/4) {
        int4 d = __ldg(&dst4[e]);
        atomicAdd(&g_deg[d.x], 1);
        atomicAdd(&g_deg[d.y], 1);
        atomicAdd(&g_deg[d.z], 1);
        atomicAdd(&g_deg[d.w], 1);
    }
}

__global__ void k_hist() {
    int v = blockIdx.x*blockDim.x + threadIdx.x;
    if (v < NN/4) {
        int4 d = *(const int4*)&g_deg[v*4];
        atomicAdd(&g_bins[d.x > NBIN-1 ? NBIN-1 : d.x], 1);
        atomicAdd(&g_bins[d.y > NBIN-1 ? NBIN-1 : d.y], 1);
        atomicAdd(&g_bins[d.z > NBIN-1 ? NBIN-1 : d.z], 1);
        atomicAdd(&g_bins[d.w > NBIN-1 ? NBIN-1 : d.w], 1);
    }
}

// dual exclusive scan of bins: node counts (hi 32) and edge counts cnt*deg (lo 32),
// packed in one 64-bit scan. 1024 threads = NBIN.
__global__ void k_binscan() {
    __shared__ unsigned long long wsum[32];
    int t = threadIdx.x;
    int lane = t & 31, w = t >> 5;
    int cnt = g_bins[t];
    unsigned long long val = ((unsigned long long)(unsigned)cnt << 32)
                           | (unsigned)(cnt * t);
    unsigned long long inc = val;
    #pragma unroll
    for (int o = 1; o < 32; o <<= 1) {
        unsigned long long x = __shfl_up_sync(0xffffffffu, inc, o);
        if (lane >= o) inc += x;
    }
    if (lane == 31) wsum[w] = inc;
    __syncthreads();
    if (w == 0) {
        unsigned long long x = wsum[lane];
        unsigned long long xi = x;
        #pragma unroll
        for (int o = 1; o < 32; o <<= 1) {
            unsigned long long y = __shfl_up_sync(0xffffffffu, xi, o);
            if (lane >= o) xi += y;
        }
        wsum[lane] = xi - x;   // exclusive
    }
    __syncthreads();
    unsigned long long ex = inc - val + wsum[w];
    int nodebase = (int)(ex >> 32);
    int edgebase = (int)(ex & 0xffffffffu);
    g_binnode[t] = nodebase;
    g_bincur[t]  = nodebase;
    g_binedge[t] = edgebase;
}

// scatter nodes into degree-sorted order; build perm/inv/snorm AND rowptr
// analytically: all nodes in bin b have degree b (NBIN=1024 >> max degree).
__global__ void k_perm() {
    int v = blockIdx.x*blockDim.x + threadIdx.x;
    if (v >= NN) return;
    int d = g_deg[v];
    int b = d > NBIN-1 ? NBIN-1 : d;
    int p = atomicAdd(&g_bincur[b], 1);
    g_perm[p] = v;
    g_inv[v] = p;
    g_snorm[p] = rsqrtf((float)(d > 0 ? d : 1));
    int rp = g_binedge[b] + (p - g_binnode[b]) * d;
    g_srowptr[p] = rp;
    g_scursor[p] = rp;
    if (v == 0) g_srowptr[NN] = NE;
}

// fill sorted CSR: edges land in row inv[dst], storing sorted src ids
__global__ void k_fill(const int* __restrict__ src, const int* __restrict__ dst) {
    int e = blockIdx.x*blockDim.x + threadIdx.x;
    if (e < NE) {
        int p = g_inv[dst[e]];
        int pos = atomicAdd(&g_scursor[p], 1);
        g_scolidx[pos] = g_inv[src[e]];
    }
}

__global__ void k_zero2() {
    int g = blockIdx.x*blockDim.x + threadIdx.x;
    if (g < NH4) {
        uint4 z = make_uint4(0u,0u,0u,0u);
        g_h0[g] = z;
        g_baseh[g] = z;
    }
}

// error[mask] = onehot(y_true) - y_soft[mask]; last occurrence wins (mask sorted).
// Writes into SORTED space at inv[m]. Fused sigma (run-length weighted) + labmask.
__global__ void k_scatter1(const float* __restrict__ y_soft,
                           const int* __restrict__ mask,
                           const int* __restrict__ y_true) {
    __shared__ float sh[256];
    int g = blockIdx.x*blockDim.x + threadIdx.x;
    float contrib = 0.f;
    if (g < NT*NC) {
        int i = g / NC, c = g - NC*i;
        int m = mask[i];
        bool last = (i == NT-1) || (mask[i+1] != m);
        if (last) {
            int p = g_inv[m];
            int yt = y_true[i];
            float err = ((c == yt) ? 1.0f : 0.0f) - y_soft[m*NC + c];
            ((__half*)g_h0)[p*NC + c]    = __float2half_rn(err * g_snorm[p]);
            ((__half*)g_baseh)[p*NC + c] = __float2half_rn((1.0f - ALPHA_C) * err);
            if (c == 0) g_labmask[p] = yt + 1;
            int r = 1, k = i;
            while (k > 0 && mask[k-1] == m) { r++; k--; }
            contrib = (float)r * fabsf(err);
        }
    }
    sh[threadIdx.x] = contrib;
    __syncthreads();
    for (int o = 128; o; o >>= 1) {
        if (threadIdx.x < o) sh[threadIdx.x] += sh[threadIdx.x + o];
        __syncthreads();
    }
    if (threadIdx.x == 0 && sh[0] != 0.f) atomicAdd(&g_sigma, (double)sh[0]);
}

// one propagation layer (sorted space, fp16 h + fp16 base)
// LPT order: gid 0 maps to the HIGHEST-degree end (g = NH4-1-gid).
__global__ void k_prop(const uint4* __restrict__ hin,
                       uint4* __restrict__ hout,
                       float4* __restrict__ yout,
                       const int* __restrict__ outmap,
                       float alpha, float lo, float hi) {
    int gid = blockIdx.x*blockDim.x + threadIdx.x;
    if (gid >= NH4) return;
    int g = NH4 - 1 - gid;          // descending degree order (LPT)
    int v = g / HJ;
    int j = g - v*HJ;
    int s = __ldg(&g_srowptr[v]);
    int e = __ldg(&g_srowptr[v+1]);
    float2 a0 = make_float2(0.f,0.f), a1 = a0, a2 = a0, a3 = a0;
    #pragma unroll 4
    for (int k = s; k < e; k++) {
        int u = __ldg(&g_scolidx[k]);
        uint4 t = __ldg(&hin[u*HJ + j]);
        float2 f;
        f = __half22float2(*reinterpret_cast<const __half2*>(&t.x)); a0.x += f.x; a0.y += f.y;
        f = __half22float2(*reinterpret_cast<const __half2*>(&t.y)); a1.x += f.x; a1.y += f.y;
        f = __half22float2(*reinterpret_cast<const __half2*>(&t.z)); a2.x += f.x; a2.y += f.y;
        f = __half22float2(*reinterpret_cast<const __half2*>(&t.w)); a3.x += f.x; a3.y += f.y;
    }
    float nv = __ldg(&g_snorm[v]);
    float a = alpha * nv;
    uint4 bh = __ldg(&g_baseh[g]);
    float2 b0 = __half22float2(*reinterpret_cast<const __half2*>(&bh.x));
    float2 b1 = __half22float2(*reinterpret_cast<const __half2*>(&bh.y));
    float2 b2 = __half22float2(*reinterpret_cast<const __half2*>(&bh.z));
    float2 b3 = __half22float2(*reinterpret_cast<const __half2*>(&bh.w));
    float y0 = fminf(fmaxf(fmaf(a, a0.x, b0.x), lo), hi);
    float y1 = fminf(fmaxf(fmaf(a, a0.y, b0.y), lo), hi);
    float y2 = fminf(fmaxf(fmaf(a, a1.x, b1.x), lo), hi);
    float y3 = fminf(fmaxf(fmaf(a, a1.y, b1.y), lo), hi);
    float y4 = fminf(fmaxf(fmaf(a, a2.x, b2.x), lo), hi);
    float y5 = fminf(fmaxf(fmaf(a, a2.y, b2.y), lo), hi);
    float y6 = fminf(fmaxf(fmaf(a, a3.x, b3.x), lo), hi);
    float y7 = fminf(fmaxf(fmaf(a, a3.y, b3.y), lo), hi);
    if (yout) {
        int ov = outmap ? __ldg(&outmap[v]) : v;
        yout[ov*CJ + j*2]     = make_float4(y0, y1, y2, y3);
        yout[ov*CJ + j*2 + 1] = make_float4(y4, y5, y6, y7);
    }
    if (hout) {
        __half2 h0 = __floats2half2_rn(y0*nv, y1*nv);
        __half2 h1 = __floats2half2_rn(y2*nv, y3*nv);
        __half2 h2 = __floats2half2_rn(y4*nv, y5*nv);
        __half2 h3 = __floats2half2_rn(y6*nv, y7*nv);
        uint4 o;
        o.x = *reinterpret_cast<unsigned*>(&h0);
        o.y = *reinterpret_cast<unsigned*>(&h1);
        o.z = *reinterpret_cast<unsigned*>(&h2);
        o.w = *reinterpret_cast<unsigned*>(&h3);
        hout[g] = o;
    }
}

// fused scale + apply + mask-overwrite: one thread per sorted node.
// unmasked: y1 = y_soft[perm[v]] + s*smoothed_error, s = sigma/NT/denom
// masked:   y1 = onehot(label)
// emits h0 = fp16(y1*nv), baseh = fp16((1-AS)*y1)
__global__ void k_scaleapply(const float* __restrict__ y_soft) {
    int v = blockIdx.x*blockDim.x + threadIdx.x;
    if (v >= NN) return;
    float nv = g_snorm[v];
    const float oma = 1.0f - ALPHA_S;
    uint2* hp = (uint2*)g_h0 + v*CJ;
    uint2* bp = (uint2*)g_baseh + v*CJ;
    int lab = g_labmask[v];
    if (lab) {
        int cl = lab - 1;
        #pragma unroll
        for (int j = 0; j < CJ; j++) {
            float v0 = (j*4+0 == cl) ? 1.f : 0.f;
            float v1 = (j*4+1 == cl) ? 1.f : 0.f;
            float v2 = (j*4+2 == cl) ? 1.f : 0.f;
            float v3 = (j*4+3 == cl) ? 1.f : 0.f;
            __half2 p0 = __floats2half2_rn(v0*nv, v1*nv);
            __half2 p1 = __floats2half2_rn(v2*nv, v3*nv);
            uint2 hw; hw.x = *(unsigned*)&p0; hw.y = *(unsigned*)&p1;
            hp[j] = hw;
            __half2 q0 = __floats2half2_rn(oma*v0, oma*v1);
            __half2 q1 = __floats2half2_rn(oma*v2, oma*v3);
            uint2 bw; bw.x = *(unsigned*)&q0; bw.y = *(unsigned*)&q1;
            bp[j] = bw;
        }
    } else {
        float4 se[CJ];
        float denom = 0.f;
        #pragma unroll
        for (int j = 0; j < CJ; j++) {
            se[j] = g_y[v*CJ + j];
            denom += fabsf(se[j].x) + fabsf(se[j].y) + fabsf(se[j].z) + fabsf(se[j].w);
        }
        float sig = (float)g_sigma / (float)NT;
        float s = sig / denom;
        if (isinf(s) || s > 1000.0f) s = 1.0f;
        int ov = __ldg(&g_perm[v]);
        const float4* ysp = (const float4*)(y_soft + ov*NC);
        #pragma unroll
        for (int j = 0; j < CJ; j++) {
            float4 ys = __ldg(&ysp[j]);
            float x0 = fmaf(s, se[j].x, ys.x);
            float x1 = fmaf(s, se[j].y, ys.y);
            float x2 = fmaf(s, se[j].z, ys.z);
            float x3 = fmaf(s, se[j].w, ys.w);
            __half2 p0 = __floats2half2_rn(x0*nv, x1*nv);
            __half2 p1 = __floats2half2_rn(x2*nv, x3*nv);
            uint2 hw; hw.x = *(unsigned*)&p0; hw.y = *(unsigned*)&p1;
            hp[j] = hw;
            __half2 q0 = __floats2half2_rn(oma*x0, oma*x1);
            __half2 q1 = __floats2half2_rn(oma*x2, oma*x3);
            uint2 bw; bw.x = *(unsigned*)&q0; bw.y = *(unsigned*)&q1;
            bp[j] = bw;
        }
    }
}

extern "C" void kernel_launch(void* const* d_in, const int* in_sizes, int n_in,
                              void* d_out, int out_size) {
    const float* y_soft_f = (const float*)d_in[0];
    const int* src    = (const int*)d_in[1];
    const int* dst    = (const int*)d_in[2];
    const int* y_true = (const int*)d_in[3];
    const int* mask   = (const int*)d_in[4];

    uint4 *h0, *h1;
    float4 *yb;
    int *permp;
    cudaGetSymbolAddress((void**)&h0, g_h0);
    cudaGetSymbolAddress((void**)&h1, g_h1);
    cudaGetSymbolAddress((void**)&yb, g_y);
    cudaGetSymbolAddress((void**)&permp, g_perm);

    const int B = 256;
    const int GN  = (NN + B - 1) / B;
    const int GE  = (NE + B - 1) / B;
    const int GE4 = (NE/4 + B - 1) / B;
    const int GN4 = (NN/4 + B - 1) / B;
    const int GH  = (NH4 + B - 1) / B;
    const int GTC = (NT*NC + B - 1) / B;

    // ---- build degree-sorted permutation + CSR (analytic rowptr) ----
    k_init<<<GN, B>>>();
    k_count<<<GE4, B>>>((const int4*)dst);
    k_hist<<<GN4, B>>>();
    k_binscan<<<1, NBIN>>>();
    k_perm<<<GN, B>>>();
    k_fill<<<GE, B>>>(src, dst);

    // ---- correct phase ----
    k_zero2<<<GH, B>>>();
    k_scatter1<<<GTC, B>>>(y_soft_f, mask, y_true);
    for (int i = 0; i < 9; i++)
        k_prop<<<GH, B>>>((i & 1) ? h1 : h0, (i & 1) ? h0 : h1, nullptr, nullptr,
                          ALPHA_C, -1.0f, 1.0f);
    k_prop<<<GH, B>>>(h1, nullptr, yb, nullptr, ALPHA_C, -1.0f, 1.0f);  // -> g_y (sorted)

    // ---- fused scale + apply + re-mask ----
    k_scaleapply<<<GN, B>>>(y_soft_f);

    // ---- smooth phase ----
    for (int i = 0; i < 9; i++)
        k_prop<<<GH, B>>>((i & 1) ? h1 : h0, (i & 1) ? h0 : h1, nullptr, nullptr,
                          ALPHA_S, 0.0f, 1.0f);
    k_prop<<<GH, B>>>(h1, nullptr, (float4*)d_out, permp, ALPHA_S, 0.0f, 1.0f);
}

// round 11
// speedup vs baseline: 1.1299x; 1.0009x over previous
#include <cuda_runtime.h>
#include <cuda_fp16.h>
#include <math.h>

#define NN 100000
#define NE 1600000
#define NC 40
#define CJ 10              // 40 floats = 10 float4 chunks (fp32 buffers)
#define HJ 5               // 40 halves = 5 uint4 chunks (fp16 buffers)
#define NT 50000
#define NC4 (NN*CJ)
#define NH4 (NN*HJ)
#define NBIN 1024

#define ALPHA_C 0.979f
#define ALPHA_S 0.756f

// ---- scratch (static device globals: allocation-free) ----
static __device__ int    g_deg[NN];       // original-space degree
static __device__ int    g_perm[NN];      // sorted pos -> original id
static __device__ int    g_inv[NN];       // original id -> sorted pos
static __device__ float  g_snorm[NN];     // sorted-space norm
static __device__ int    g_srowptr[NN+1];
static __device__ int    g_scursor[NN];
static __device__ int    g_scolidx[NE];   // sorted ids
static __device__ int    g_labmask[NN];   // sorted space: 0 = unmasked, else y_true+1
static __device__ uint4  g_h0[NH4];       // fp16 feature buffer (ping), sorted space
static __device__ uint4  g_h1[NH4];       // fp16 feature buffer (pong), sorted space
static __device__ uint4  g_baseh[NH4];    // fp16 (1-alpha)*y0 anchor, sorted space
static __device__ float4 g_y[NC4];        // smoothed_error (fp32), sorted space
static __device__ int    g_bins[NBIN];
static __device__ int    g_bincur[NBIN];  // mutable node cursor per bin
static __device__ int    g_binnode[NBIN]; // node-exclusive prefix per bin
static __device__ int    g_binedge[NBIN]; // edge-exclusive prefix per bin
static __device__ double g_sigma;

__global__ void k_init() {
    int v = blockIdx.x*blockDim.x + threadIdx.x;
    if (v < NN) { g_deg[v] = 0; g_labmask[v] = 0; }
    if (v < NBIN) g_bins[v] = 0;
    if (v == 0) g_sigma = 0.0;
}

// count in-degree, 4 edges per thread
__global__ void k_count(const int4* __restrict__ dst4) {
    int e = blockIdx.x*blockDim.x + threadIdx.x;
    if (e < NE/4) {
        int4 d = __ldg(&dst4[e]);
        atomicAdd(&g_deg[d.x], 1);
        atomicAdd(&g_deg[d.y], 1);
        atomicAdd(&g_deg[d.z], 1);
        atomicAdd(&g_deg[d.w], 1);
    }
}

__global__ void k_hist() {
    int v = blockIdx.x*blockDim.x + threadIdx.x;
    if (v < NN/4) {
        int4 d = *(const int4*)&g_deg[v*4];
        atomicAdd(&g_bins[d.x > NBIN-1 ? NBIN-1 : d.x], 1);
        atomicAdd(&g_bins[d.y > NBIN-1 ? NBIN-1 : d.y], 1);
        atomicAdd(&g_bins[d.z > NBIN-1 ? NBIN-1 : d.z], 1);
        atomicAdd(&g_bins[d.w > NBIN-1 ? NBIN-1 : d.w], 1);
    }
}

// dual exclusive scan of bins: node counts (hi 32) and edge counts cnt*deg (lo 32),
// packed in one 64-bit scan. 1024 threads = NBIN.
__global__ void k_binscan() {
    __shared__ unsigned long long wsum[32];
    int t = threadIdx.x;
    int lane = t & 31, w = t >> 5;
    int cnt = g_bins[t];
    unsigned long long val = ((unsigned long long)(unsigned)cnt << 32)
                           | (unsigned)(cnt * t);
    unsigned long long inc = val;
    #pragma unroll
    for (int o = 1; o < 32; o <<= 1) {
        unsigned long long x = __shfl_up_sync(0xffffffffu, inc, o);
        if (lane >= o) inc += x;
    }
    if (lane == 31) wsum[w] = inc;
    __syncthreads();
    if (w == 0) {
        unsigned long long x = wsum[lane];
        unsigned long long xi = x;
        #pragma unroll
        for (int o = 1; o < 32; o <<= 1) {
            unsigned long long y = __shfl_up_sync(0xffffffffu, xi, o);
            if (lane >= o) xi += y;
        }
        wsum[lane] = xi - x;   // exclusive
    }
    __syncthreads();
    unsigned long long ex = inc - val + wsum[w];
    int nodebase = (int)(ex >> 32);
    int edgebase = (int)(ex & 0xffffffffu);
    g_binnode[t] = nodebase;
    g_bincur[t]  = nodebase;
    g_binedge[t] = edgebase;
}

// scatter nodes into degree-sorted order; build perm/inv/snorm AND rowptr
// analytically: all nodes in bin b have degree b (NBIN=1024 >> max degree).
__global__ void k_perm() {
    int v = blockIdx.x*blockDim.x + threadIdx.x;
    if (v >= NN) return;
    int d = g_deg[v];
    int b = d > NBIN-1 ? NBIN-1 : d;
    int p = atomicAdd(&g_bincur[b], 1);
    g_perm[p] = v;
    g_inv[v] = p;
    g_snorm[p] = rsqrtf((float)(d > 0 ? d : 1));
    int rp = g_binedge[b] + (p - g_binnode[b]) * d;
    g_srowptr[p] = rp;
    g_scursor[p] = rp;
    if (v == 0) g_srowptr[NN] = NE;
}

// fill sorted CSR: edges land in row inv[dst], storing sorted src ids
__global__ void k_fill(const int* __restrict__ src, const int* __restrict__ dst) {
    int e = blockIdx.x*blockDim.x + threadIdx.x;
    if (e < NE) {
        int p = g_inv[dst[e]];
        int pos = atomicAdd(&g_scursor[p], 1);
        g_scolidx[pos] = g_inv[src[e]];
    }
}

__global__ void k_zero2() {
    int g = blockIdx.x*blockDim.x + threadIdx.x;
    if (g < NH4) {
        uint4 z = make_uint4(0u,0u,0u,0u);
        g_h0[g] = z;
        g_baseh[g] = z;
    }
}

// error[mask] = onehot(y_true) - y_soft[mask]; last occurrence wins (mask sorted).
// Writes into SORTED space at inv[m]. Fused sigma (run-length weighted) + labmask.
__global__ void k_scatter1(const float* __restrict__ y_soft,
                           const int* __restrict__ mask,
                           const int* __restrict__ y_true) {
    __shared__ float sh[256];
    int g = blockIdx.x*blockDim.x + threadIdx.x;
    float contrib = 0.f;
    if (g < NT*NC) {
        int i = g / NC, c = g - NC*i;
        int m = mask[i];
        bool last = (i == NT-1) || (mask[i+1] != m);
        if (last) {
            int p = g_inv[m];
            int yt = y_true[i];
            float err = ((c == yt) ? 1.0f : 0.0f) - y_soft[m*NC + c];
            ((__half*)g_h0)[p*NC + c]    = __float2half_rn(err * g_snorm[p]);
            ((__half*)g_baseh)[p*NC + c] = __float2half_rn((1.0f - ALPHA_C) * err);
            if (c == 0) g_labmask[p] = yt + 1;
            int r = 1, k = i;
            while (k > 0 && mask[k-1] == m) { r++; k--; }
            contrib = (float)r * fabsf(err);
        }
    }
    sh[threadIdx.x] = contrib;
    __syncthreads();
    for (int o = 128; o; o >>= 1) {
        if (threadIdx.x < o) sh[threadIdx.x] += sh[threadIdx.x + o];
        __syncthreads();
    }
    if (threadIdx.x == 0 && sh[0] != 0.f) atomicAdd(&g_sigma, (double)sh[0]);
}

// one propagation layer (sorted space, fp16 h + fp16 base)
// LPT order: gid 0 maps to the HIGHEST-degree end (g = NH4-1-gid).
__global__ void k_prop(const uint4* __restrict__ hin,
                       uint4* __restrict__ hout,
                       float4* __restrict__ yout,
                       const int* __restrict__ outmap,
                       float alpha, float lo, float hi) {
    int gid = blockIdx.x*blockDim.x + threadIdx.x;
    if (gid >= NH4) return;
    int g = NH4 - 1 - gid;          // descending degree order (LPT)
    int v = g / HJ;
    int j = g - v*HJ;
    int s = __ldg(&g_srowptr[v]);
    int e = __ldg(&g_srowptr[v+1]);
    float2 a0 = make_float2(0.f,0.f), a1 = a0, a2 = a0, a3 = a0;
    #pragma unroll 4
    for (int k = s; k < e; k++) {
        int u = __ldg(&g_scolidx[k]);
        uint4 t = __ldg(&hin[u*HJ + j]);
        float2 f;
        f = __half22float2(*reinterpret_cast<const __half2*>(&t.x)); a0.x += f.x; a0.y += f.y;
        f = __half22float2(*reinterpret_cast<const __half2*>(&t.y)); a1.x += f.x; a1.y += f.y;
        f = __half22float2(*reinterpret_cast<const __half2*>(&t.z)); a2.x += f.x; a2.y += f.y;
        f = __half22float2(*reinterpret_cast<const __half2*>(&t.w)); a3.x += f.x; a3.y += f.y;
    }
    float nv = __ldg(&g_snorm[v]);
    float a = alpha * nv;
    uint4 bh = __ldg(&g_baseh[g]);
    float2 b0 = __half22float2(*reinterpret_cast<const __half2*>(&bh.x));
    float2 b1 = __half22float2(*reinterpret_cast<const __half2*>(&bh.y));
    float2 b2 = __half22float2(*reinterpret_cast<const __half2*>(&bh.z));
    float2 b3 = __half22float2(*reinterpret_cast<const __half2*>(&bh.w));
    float y0 = fminf(fmaxf(fmaf(a, a0.x, b0.x), lo), hi);
    float y1 = fminf(fmaxf(fmaf(a, a0.y, b0.y), lo), hi);
    float y2 = fminf(fmaxf(fmaf(a, a1.x, b1.x), lo), hi);
    float y3 = fminf(fmaxf(fmaf(a, a1.y, b1.y), lo), hi);
    float y4 = fminf(fmaxf(fmaf(a, a2.x, b2.x), lo), hi);
    float y5 = fminf(fmaxf(fmaf(a, a2.y, b2.y), lo), hi);
    float y6 = fminf(fmaxf(fmaf(a, a3.x, b3.x), lo), hi);
    float y7 = fminf(fmaxf(fmaf(a, a3.y, b3.y), lo), hi);
    if (yout) {
        int ov = outmap ? __ldg(&outmap[v]) : v;
        yout[ov*CJ + j*2]     = make_float4(y0, y1, y2, y3);
        yout[ov*CJ + j*2 + 1] = make_float4(y4, y5, y6, y7);
    }
    if (hout) {
        __half2 h0 = __floats2half2_rn(y0*nv, y1*nv);
        __half2 h1 = __floats2half2_rn(y2*nv, y3*nv);
        __half2 h2 = __floats2half2_rn(y4*nv, y5*nv);
        __half2 h3 = __floats2half2_rn(y6*nv, y7*nv);
        uint4 o;
        o.x = *reinterpret_cast<unsigned*>(&h0);
        o.y = *reinterpret_cast<unsigned*>(&h1);
        o.z = *reinterpret_cast<unsigned*>(&h2);
        o.w = *reinterpret_cast<unsigned*>(&h3);
        hout[g] = o;
    }
}

// fused scale + apply + mask-overwrite: one thread per sorted node.
// unmasked: y1 = y_soft[perm[v]] + s*smoothed_error, s = sigma/NT/denom
// masked:   y1 = onehot(label)
// emits h0 = fp16(y1*nv), baseh = fp16((1-AS)*y1)
__global__ void k_scaleapply(const float* __restrict__ y_soft) {
    int v = blockIdx.x*blockDim.x + threadIdx.x;
    if (v >= NN) return;
    float nv = g_snorm[v];
    const float oma = 1.0f - ALPHA_S;
    uint2* hp = (uint2*)g_h0 + v*CJ;
    uint2* bp = (uint2*)g_baseh + v*CJ;
    int lab = g_labmask[v];
    if (lab) {
        int cl = lab - 1;
        #pragma unroll
        for (int j = 0; j < CJ; j++) {
            float v0 = (j*4+0 == cl) ? 1.f : 0.f;
            float v1 = (j*4+1 == cl) ? 1.f : 0.f;
            float v2 = (j*4+2 == cl) ? 1.f : 0.f;
            float v3 = (j*4+3 == cl) ? 1.f : 0.f;
            __half2 p0 = __floats2half2_rn(v0*nv, v1*nv);
            __half2 p1 = __floats2half2_rn(v2*nv, v3*nv);
            uint2 hw; hw.x = *(unsigned*)&p0; hw.y = *(unsigned*)&p1;
            hp[j] = hw;
            __half2 q0 = __floats2half2_rn(oma*v0, oma*v1);
            __half2 q1 = __floats2half2_rn(oma*v2, oma*v3);
            uint2 bw; bw.x = *(unsigned*)&q0; bw.y = *(unsigned*)&q1;
            bp[j] = bw;
        }
    } else {
        float4 se[CJ];
        float denom = 0.f;
        #pragma unroll
        for (int j = 0; j < CJ; j++) {
            se[j] = g_y[v*CJ + j];
            denom += fabsf(se[j].x) + fabsf(se[j].y) + fabsf(se[j].z) + fabsf(se[j].w);
        }
        float sig = (float)g_sigma / (float)NT;
        float s = sig / denom;
        if (isinf(s) || s > 1000.0f) s = 1.0f;
        int ov = __ldg(&g_perm[v]);
        const float4* ysp = (const float4*)(y_soft + ov*NC);
        #pragma unroll
        for (int j = 0; j < CJ; j++) {
            float4 ys = __ldg(&ysp[j]);
            float x0 = fmaf(s, se[j].x, ys.x);
            float x1 = fmaf(s, se[j].y, ys.y);
            float x2 = fmaf(s, se[j].z, ys.z);
            float x3 = fmaf(s, se[j].w, ys.w);
            __half2 p0 = __floats2half2_rn(x0*nv, x1*nv);
            __half2 p1 = __floats2half2_rn(x2*nv, x3*nv);
            uint2 hw; hw.x = *(unsigned*)&p0; hw.y = *(unsigned*)&p1;
            hp[j] = hw;
            __half2 q0 = __floats2half2_rn(oma*x0, oma*x1);
            __half2 q1 = __floats2half2_rn(oma*x2, oma*x3);
            uint2 bw; bw.x = *(unsigned*)&q0; bw.y = *(unsigned*)&q1;
            bp[j] = bw;
        }
    }
}

extern "C" void kernel_launch(void* const* d_in, const int* in_sizes, int n_in,
                              void* d_out, int out_size) {
    const float* y_soft_f = (const float*)d_in[0];
    const int* src    = (const int*)d_in[1];
    const int* dst    = (const int*)d_in[2];
    const int* y_true = (const int*)d_in[3];
    const int* mask   = (const int*)d_in[4];

    uint4 *h0, *h1;
    float4 *yb;
    int *permp;
    cudaGetSymbolAddress((void**)&h0, g_h0);
    cudaGetSymbolAddress((void**)&h1, g_h1);
    cudaGetSymbolAddress((void**)&yb, g_y);
    cudaGetSymbolAddress((void**)&permp, g_perm);

    const int B = 256;
    const int GN  = (NN + B - 1) / B;
    const int GE  = (NE + B - 1) / B;
    const int GE4 = (NE/4 + B - 1) / B;
    const int GN4 = (NN/4 + B - 1) / B;
    const int GH  = (NH4 + B - 1) / B;
    const int GTC = (NT*NC + B - 1) / B;

    // ---- build degree-sorted permutation + CSR (analytic rowptr) ----
    k_init<<<GN, B>>>();
    k_count<<<GE4, B>>>((const int4*)dst);
    k_hist<<<GN4, B>>>();
    k_binscan<<<1, NBIN>>>();
    k_perm<<<GN, B>>>();
    k_fill<<<GE, B>>>(src, dst);

    // ---- correct phase ----
    k_zero2<<<GH, B>>>();
    k_scatter1<<<GTC, B>>>(y_soft_f, mask, y_true);
    for (int i = 0; i < 9; i++)
        k_prop<<<GH, B>>>((i & 1) ? h1 : h0, (i & 1) ? h0 : h1, nullptr, nullptr,
                          ALPHA_C, -1.0f, 1.0f);
    k_prop<<<GH, B>>>(h1, nullptr, yb, nullptr, ALPHA_C, -1.0f, 1.0f);  // -> g_y (sorted)

    // ---- fused scale + apply + re-mask ----
    k_scaleapply<<<GN, B>>>(y_soft_f);

    // ---- smooth phase ----
    for (int i = 0; i < 9; i++)
        k_prop<<<GH, B>>>((i & 1) ? h1 : h0, (i & 1) ? h0 : h1, nullptr, nullptr,
                          ALPHA_S, 0.0f, 1.0f);
    k_prop<<<GH, B>>>(h1, nullptr, (float4*)d_out, permp, ALPHA_S, 0.0f, 1.0f);
}